// round 2
// baseline (speedup 1.0000x reference)
#include <cuda_runtime.h>
#include <cstdint>

// ---------------- constants ----------------
// B=16, T=2048, C=512, H=256, NO=5, R=8

// ---------------- device scratch ----------------
__device__ float g_musig0[32768 * 5 * 2];   // d-tile 0 partials, then combined (mu,sig)
__device__ float g_musig1[32768 * 5 * 2];   // d-tile 1 partials
__device__ float g_smpart[16 * 5 * 16 * 2]; // [b][head][mblk][dtile] partial h.ws sums
__device__ float g_gauss[16 * 5 * 17];      // normalized gaussian kernels per (b, head)

// ---------------- threefry2x32 (JAX-compatible) ----------------
__host__ __device__ __forceinline__ uint32_t rotl32(uint32_t x, uint32_t r) {
    return (x << r) | (x >> (32u - r));
}
__host__ __device__ __forceinline__ void threefry2x32(
    uint32_t k0, uint32_t k1, uint32_t x0, uint32_t x1,
    uint32_t& o0, uint32_t& o1)
{
    uint32_t k2 = k0 ^ k1 ^ 0x1BD11BDAu;
    x0 += k0; x1 += k1;
#define TF_R(r) { x0 += x1; x1 = rotl32(x1, r); x1 ^= x0; }
    TF_R(13) TF_R(15) TF_R(26) TF_R(6)   x0 += k1; x1 += k2 + 1u;
    TF_R(17) TF_R(29) TF_R(16) TF_R(24)  x0 += k2; x1 += k0 + 2u;
    TF_R(13) TF_R(15) TF_R(26) TF_R(6)   x0 += k0; x1 += k1 + 3u;
    TF_R(17) TF_R(29) TF_R(16) TF_R(24)  x0 += k1; x1 += k2 + 4u;
    TF_R(13) TF_R(15) TF_R(26) TF_R(6)   x0 += k2; x1 += k0 + 5u;
#undef TF_R
    o0 = x0; o1 = x1;
}

// partitionable threefry 32-bit draw -> standard normal (JAX-exact recipe)
__device__ __forceinline__ float bits_to_normal(uint32_t bits) {
    float f = __uint_as_float((bits >> 9) | 0x3f800000u) - 1.0f;  // [0,1)
    const float LO = -0.99999994f;                                 // nextafter(-1,0)
    float u = fmaf(f, 2.0f, LO);                                   // *2 exact -> fma == mul+add
    u = fmaxf(LO, u);
    return 1.41421356237f * erfinvf(u);
}

__device__ __forceinline__ float gelu_exact(float v) {
    return 0.5f * v * (1.0f + erff(v * 0.70710678118654752f));
}

// ---------------- Phase 1: fused GEMM (x@w1 + b1 -> gelu) + rank-2/rank-1 epilogue ----------------
// M = 32768, K = 512, per-head N = 256 split into two 128-wide d-tiles.
// grid = (256, 10): blockIdx.x = m-block (128 rows), blockIdx.y = head*2 + dtile.
__global__ __launch_bounds__(256) void gemm_kernel(
    const float* __restrict__ x, const float* __restrict__ w1,
    const float* __restrict__ b1, const float* __restrict__ w2,
    const float* __restrict__ ws)
{
    __shared__ float As[16][132];
    __shared__ float Bs[16][128];
    __shared__ float sred[16];

    int tid = threadIdx.x;
    int tx = tid & 15, ty = tid >> 4;
    int bx = blockIdx.x;
    int ntile = blockIdx.y;
    int head = ntile >> 1;
    int dtile = ntile & 1;
    int d0 = dtile * 128;

    const float* Ap = x + (size_t)bx * 128 * 512;
    const float* Bp = w1 + (size_t)head * 512 * 256 + d0;

    float acc[8][8];
#pragma unroll
    for (int i = 0; i < 8; i++)
#pragma unroll
        for (int j = 0; j < 8; j++) acc[i][j] = 0.f;

    for (int k0 = 0; k0 < 512; k0 += 16) {
#pragma unroll
        for (int it = 0; it < 2; it++) {
            int p = tid + it * 256;
            int row = p >> 2;
            int kk = (p & 3) * 4;
            float4 v = *(const float4*)(Ap + (size_t)row * 512 + k0 + kk);
            As[kk + 0][row] = v.x; As[kk + 1][row] = v.y;
            As[kk + 2][row] = v.z; As[kk + 3][row] = v.w;
        }
#pragma unroll
        for (int it = 0; it < 2; it++) {
            int p = tid + it * 256;
            int kk = p >> 5;
            int dd = (p & 31) * 4;
            *(float4*)&Bs[kk][dd] = *(const float4*)(Bp + (size_t)(k0 + kk) * 256 + dd);
        }
        __syncthreads();
#pragma unroll
        for (int kk = 0; kk < 16; kk++) {
            float a[8], b[8];
            *(float4*)&a[0] = *(const float4*)&As[kk][ty * 4];
            *(float4*)&a[4] = *(const float4*)&As[kk][64 + ty * 4];
            *(float4*)&b[0] = *(const float4*)&Bs[kk][tx * 4];
            *(float4*)&b[4] = *(const float4*)&Bs[kk][64 + tx * 4];
#pragma unroll
            for (int i = 0; i < 8; i++)
#pragma unroll
                for (int j = 0; j < 8; j++)
                    acc[i][j] = fmaf(a[i], b[j], acc[i][j]);
        }
        __syncthreads();
    }

    // epilogue: gelu then contract against w2 (2 cols) and ws (1 col)
    float w20[8], w21[8], wsv[8], b1v[8];
#pragma unroll
    for (int jj = 0; jj < 8; jj++) {
        int col = (jj < 4) ? (tx * 4 + jj) : (64 + tx * 4 + jj - 4);
        int d = d0 + col;
        w20[jj] = w2[d * 2 + 0];
        w21[jj] = w2[d * 2 + 1];
        wsv[jj] = ws[d];
        b1v[jj] = b1[head * 256 + d];
    }

    float psm_tot = 0.f;
#pragma unroll
    for (int rr = 0; rr < 8; rr++) {
        int m = bx * 128 + ((rr < 4) ? (ty * 4 + rr) : (64 + ty * 4 + rr - 4));
        float pmu = 0.f, psig = 0.f, psm = 0.f;
#pragma unroll
        for (int jj = 0; jj < 8; jj++) {
            float h = gelu_exact(acc[rr][jj] + b1v[jj]);
            pmu  = fmaf(h, w20[jj], pmu);
            psig = fmaf(h, w21[jj], psig);
            psm  = fmaf(h, wsv[jj], psm);
        }
#pragma unroll
        for (int off = 8; off >= 1; off >>= 1) {
            pmu  += __shfl_xor_sync(0xffffffffu, pmu,  off);
            psig += __shfl_xor_sync(0xffffffffu, psig, off);
            psm  += __shfl_xor_sync(0xffffffffu, psm,  off);
        }
        if (tx == 0) {
            float* dst = dtile ? g_musig1 : g_musig0;
            dst[((size_t)m * 5 + head) * 2 + 0] = pmu;
            dst[((size_t)m * 5 + head) * 2 + 1] = psig;
            psm_tot += psm;
        }
    }
    if (tx == 0) sred[ty] = psm_tot;
    __syncthreads();
    if (tid == 0) {
        float s = 0.f;
#pragma unroll
        for (int j = 0; j < 16; j++) s += sred[j];
        int b = bx >> 4, mblk = bx & 15;
        g_smpart[((b * 5 + head) * 16 + mblk) * 2 + dtile] = s;
    }
}

// ---------------- Phase 2a: combine d-tile partials + b2 into final (mu, sig) ----------------
__global__ void combine_kernel(const float* __restrict__ b2) {
    int i = blockIdx.x * 256 + threadIdx.x;   // 32768*5 = 163840 entries
    if (i >= 32768 * 5) return;
    float2* p0 = (float2*)g_musig0;
    float2* p1 = (float2*)g_musig1;
    float2 a = p0[i], c = p1[i];
    p0[i] = make_float2(a.x + c.x + b2[0], a.y + c.y + b2[1]);
}

// ---------------- Phase 2b: smooths -> normalized gaussian kernels ----------------
__global__ void reduce_gauss_kernel(const float* __restrict__ bs) {
    int id = threadIdx.x;   // one thread per (b, head): 80 used
    if (id >= 80) return;
    float s = 0.f;
#pragma unroll
    for (int j = 0; j < 32; j++) s += g_smpart[id * 32 + j];
    float sig = s * (1.0f / 2048.0f) + bs[0];
    float denom = sig * sig + 1e-6f;
    float kv[17];
    float ksum = 0.f;
#pragma unroll
    for (int d = 0; d < 17; d++) {
        float t = (float)(d - 8);
        kv[d] = expf(-0.5f * t * t / denom);
        ksum += kv[d];
    }
    float inv = 1.0f / ksum;
#pragma unroll
    for (int d = 0; d < 17; d++) g_gauss[id * 17 + d] = kv[d] * inv;
}

// ---------------- Phase 3: noise generation + temporal gaussian smoothing ----------------
// One thread: fixed (b, s), 32-long time chunk. Generates the 48-value window
// v = mu + sig*eps in registers, emits 32 outputs as 17-tap convolutions.
// Partitionable threefry: eps(e) = normal(xorfold(threefry(key, hi32(e)=0, lo32(e)=e))).
__global__ __launch_bounds__(128) void noise_kernel(
    float* __restrict__ out, int head, int S2, int s2log,
    uint32_t key0, uint32_t key1)
{
    int gid = blockIdx.x * 128 + threadIdx.x;
    int s = gid & (S2 - 1);
    int rest = gid >> s2log;
    int b = rest & 15;
    int chunk = rest >> 4;
    int t0 = chunk * 32;

    float kv[17];
#pragma unroll
    for (int d = 0; d < 17; d++)
        kv[d] = g_gauss[(b * 5 + head) * 17 + d];

    const float2* ms = (const float2*)g_musig0;

    float v[48];
#pragma unroll
    for (int j = 0; j < 48; j++) {
        int t = t0 - 8 + j;
        int tr = (t < 0) ? -t : ((t > 2047) ? (4094 - t) : t);   // reflect padding
        int m = b * 2048 + tr;
        float2 p = ms[m * 5 + head];
        uint32_t e = (uint32_t)m * (uint32_t)S2 + (uint32_t)s;   // 64-bit linear idx, hi=0
        uint32_t o0, o1;
        threefry2x32(key0, key1, 0u, e, o0, o1);
        v[j] = fmaf(p.y, bits_to_normal(o0 ^ o1), p.x);
    }

    size_t ob = ((size_t)(b * 2048 + t0)) * (size_t)S2 + (size_t)s;
#pragma unroll
    for (int o = 0; o < 32; o++) {
        float a = 0.f;
#pragma unroll
        for (int d = 0; d < 17; d++)
            a = fmaf(kv[d], v[o + d], a);
        out[ob + (size_t)o * S2] = a;
    }
}

// ---------------- launch ----------------
extern "C" void kernel_launch(void* const* d_in, const int* in_sizes, int n_in,
                              void* d_out, int out_size)
{
    // map inputs by element count (all distinct) to be robust to ordering
    const float *x = 0, *w1 = 0, *b1 = 0, *w2 = 0, *b2 = 0, *ws = 0, *bs = 0;
    for (int i = 0; i < n_in; i++) {
        switch (in_sizes[i]) {
            case 16777216: x  = (const float*)d_in[i]; break;
            case 655360:   w1 = (const float*)d_in[i]; break;
            case 1280:     b1 = (const float*)d_in[i]; break;
            case 512:      w2 = (const float*)d_in[i]; break;
            case 256:      ws = (const float*)d_in[i]; break;
            case 2:        b2 = (const float*)d_in[i]; break;
            case 1:        bs = (const float*)d_in[i]; break;
        }
    }
    float* out = (float*)d_out;

    dim3 grid(256, 10);
    gemm_kernel<<<grid, 256>>>(x, w1, b1, w2, ws);
    combine_kernel<<<640, 256>>>(b2);
    reduce_gauss_kernel<<<1, 128>>>(bs);

    size_t off = 0;
    for (int i = 0; i < 5; i++) {
        int S = 4 << i;
        int S2 = S * S;
        int s2log = 4 + 2 * i;
        // folded key: threefry2x32(key=(0,1), counts=(0,i)) == jax.random.fold_in(key(1), i)
        uint32_t f0, f1;
        threefry2x32(0u, 1u, 0u, (uint32_t)i, f0, f1);
        int total = 16 * S2 * 64;    // B * S^2 * (T/32) threads
        noise_kernel<<<total / 128, 128>>>(out + off, i, S2, s2log, f0, f1);
        off += (size_t)16 * 2048 * (size_t)S2;
    }
}

// round 3
// speedup vs baseline: 1.1617x; 1.1617x over previous
#include <cuda_runtime.h>
#include <cuda_bf16.h>
#include <cstdint>

// B=16, T=2048, C=512, H=256, NO=5, R=8

// ---------------- device scratch ----------------
__device__ float g_musig0[32768 * 5 * 2];
__device__ float g_musig1[32768 * 5 * 2];
__device__ float g_smpart[16 * 5 * 16 * 2];
__device__ float g_gauss[16 * 5 * 17];
__device__ __nv_bfloat16 g_xh[16777216];
__device__ __nv_bfloat16 g_xl[16777216];
__device__ __nv_bfloat16 g_wh[655360];   // transposed: [head][d][k]
__device__ __nv_bfloat16 g_wl[655360];

// ---------------- threefry2x32 (JAX-compatible) ----------------
__host__ __device__ __forceinline__ uint32_t rotl32(uint32_t x, uint32_t r) {
    return (x << r) | (x >> (32u - r));
}
__host__ __device__ __forceinline__ void threefry2x32(
    uint32_t k0, uint32_t k1, uint32_t x0, uint32_t x1,
    uint32_t& o0, uint32_t& o1)
{
    uint32_t k2 = k0 ^ k1 ^ 0x1BD11BDAu;
    x0 += k0; x1 += k1;
#define TF_R(r) { x0 += x1; x1 = rotl32(x1, r); x1 ^= x0; }
    TF_R(13) TF_R(15) TF_R(26) TF_R(6)   x0 += k1; x1 += k2 + 1u;
    TF_R(17) TF_R(29) TF_R(16) TF_R(24)  x0 += k2; x1 += k0 + 2u;
    TF_R(13) TF_R(15) TF_R(26) TF_R(6)   x0 += k0; x1 += k1 + 3u;
    TF_R(17) TF_R(29) TF_R(16) TF_R(24)  x0 += k1; x1 += k2 + 4u;
    TF_R(13) TF_R(15) TF_R(26) TF_R(6)   x0 += k2; x1 += k0 + 5u;
#undef TF_R
    o0 = x0; o1 = x1;
}

__device__ __forceinline__ float bits_to_normal(uint32_t bits) {
    float f = __uint_as_float((bits >> 9) | 0x3f800000u) - 1.0f;
    const float LO = -0.99999994f;
    float u = fmaf(f, 2.0f, LO);
    u = fmaxf(LO, u);
    return 1.41421356237f * erfinvf(u);
}

__device__ __forceinline__ float gelu_exact(float v) {
    return 0.5f * v * (1.0f + erff(v * 0.70710678118654752f));
}

// ---------------- PTX helpers ----------------
__device__ __forceinline__ void cp_async16(uint32_t dst, const void* src) {
    asm volatile("cp.async.cg.shared.global [%0], [%1], 16;\n" :: "r"(dst), "l"(src));
}
__device__ __forceinline__ void ldm_x4(uint32_t& r0, uint32_t& r1, uint32_t& r2, uint32_t& r3, uint32_t addr) {
    asm volatile("ldmatrix.sync.aligned.m8n8.x4.shared.b16 {%0,%1,%2,%3}, [%4];\n"
        : "=r"(r0), "=r"(r1), "=r"(r2), "=r"(r3) : "r"(addr));
}
__device__ __forceinline__ void mma16816(float* c, const uint32_t* a, uint32_t b0, uint32_t b1) {
    asm volatile(
        "mma.sync.aligned.m16n8k16.row.col.f32.bf16.bf16.f32 "
        "{%0,%1,%2,%3},{%4,%5,%6,%7},{%8,%9},{%0,%1,%2,%3};\n"
        : "+f"(c[0]), "+f"(c[1]), "+f"(c[2]), "+f"(c[3])
        : "r"(a[0]), "r"(a[1]), "r"(a[2]), "r"(a[3]), "r"(b0), "r"(b1));
}

// ---------------- Phase 0: precision-split conversions ----------------
__global__ __launch_bounds__(256) void convert_x(const float* __restrict__ x) {
    int i = (blockIdx.x * 256 + threadIdx.x) * 4;
    float4 v = *(const float4*)(x + i);
    __nv_bfloat16 h0 = __float2bfloat16_rn(v.x), h1 = __float2bfloat16_rn(v.y);
    __nv_bfloat16 h2 = __float2bfloat16_rn(v.z), h3 = __float2bfloat16_rn(v.w);
    __nv_bfloat16 l0 = __float2bfloat16_rn(v.x - __bfloat162float(h0));
    __nv_bfloat16 l1 = __float2bfloat16_rn(v.y - __bfloat162float(h1));
    __nv_bfloat16 l2 = __float2bfloat16_rn(v.z - __bfloat162float(h2));
    __nv_bfloat16 l3 = __float2bfloat16_rn(v.w - __bfloat162float(h3));
    *(__nv_bfloat162*)(g_xh + i)     = __nv_bfloat162(h0, h1);
    *(__nv_bfloat162*)(g_xh + i + 2) = __nv_bfloat162(h2, h3);
    *(__nv_bfloat162*)(g_xl + i)     = __nv_bfloat162(l0, l1);
    *(__nv_bfloat162*)(g_xl + i + 2) = __nv_bfloat162(l2, l3);
}

__global__ __launch_bounds__(256) void convert_w(const float* __restrict__ w1) {
    int idx = blockIdx.x * 256 + threadIdx.x;    // 655360 total
    if (idx >= 655360) return;
    int head = idx / (512 * 256);
    int r = idx % (512 * 256);
    int k = r / 256, d = r % 256;
    float v = w1[idx];
    __nv_bfloat16 h = __float2bfloat16_rn(v);
    __nv_bfloat16 l = __float2bfloat16_rn(v - __bfloat162float(h));
    int o = head * 131072 + d * 512 + k;
    g_wh[o] = h;
    g_wl[o] = l;
}

// ---------------- Phase 1: bf16 split tensor-core GEMM + fused epilogue ----------------
// grid = (256, 10): bx = m-block (128 rows), by = head*2 + dtile (128 d-cols).
// Logical K' = 1536: 48 stages of BK=32; term = stage/16 in {(hi,hi),(hi,lo),(lo,hi)}.
__global__ __launch_bounds__(256) void gemm_mma_kernel(
    const float* __restrict__ b1, const float* __restrict__ w2,
    const float* __restrict__ ws)
{
    __shared__ __nv_bfloat16 As[2][128 * 40];
    __shared__ __nv_bfloat16 Bs[2][128 * 40];
    __shared__ float cb1[128], cw20[128], cw21[128], cwsv[128];
    __shared__ float red[2][128][3];
    __shared__ float swred[4];

    int tid = threadIdx.x;
    int lane = tid & 31, warp = tid >> 5;
    int warpM = warp >> 1, warpN = warp & 1;
    int bx = blockIdx.x;
    int head = blockIdx.y >> 1;
    int dtile = blockIdx.y & 1;
    int d0 = dtile * 128;

    uint32_t AsBase = (uint32_t)__cvta_generic_to_shared(&As[0][0]);
    uint32_t BsBase = (uint32_t)__cvta_generic_to_shared(&Bs[0][0]);

    // epilogue constants
    if (tid < 128) {
        int d = d0 + tid;
        cb1[tid]  = b1[head * 256 + d];
        cw20[tid] = w2[d * 2 + 0];
        cw21[tid] = w2[d * 2 + 1];
        cwsv[tid] = ws[d];
    }

    int crow = tid >> 2, cc8 = (tid & 3) * 8;   // copy indexing: 2 chunks of 256

    auto issue = [&](int s, int buf) {
        int term = s >> 4;
        int k0 = (s & 15) * 32;
        const __nv_bfloat16* Asrc = (term == 2) ? g_xl : g_xh;
        const __nv_bfloat16* Bsrc = (term == 1) ? g_wl : g_wh;
#pragma unroll
        for (int it = 0; it < 2; it++) {
            int row = crow + it * 64;
            cp_async16(AsBase + buf * 10240u + (uint32_t)(row * 40 + cc8) * 2u,
                       Asrc + (size_t)(bx * 128 + row) * 512 + k0 + cc8);
            cp_async16(BsBase + buf * 10240u + (uint32_t)(row * 40 + cc8) * 2u,
                       Bsrc + (size_t)head * 131072 + (size_t)(d0 + row) * 512 + k0 + cc8);
        }
        asm volatile("cp.async.commit_group;\n");
    };

    float acc[2][8][4];
#pragma unroll
    for (int mt = 0; mt < 2; mt++)
#pragma unroll
        for (int nf = 0; nf < 8; nf++)
#pragma unroll
            for (int r = 0; r < 4; r++) acc[mt][nf][r] = 0.f;

    int lr = lane & 15, lc = (lane >> 4) * 8;   // ldmatrix lane addressing

    issue(0, 0);
    __syncthreads();   // covers cb1 etc. too

    for (int s = 0; s < 48; s++) {
        int buf = s & 1;
        if (s < 47) issue(s + 1, buf ^ 1);
        if (s < 47) { asm volatile("cp.async.wait_group 1;\n"); }
        else        { asm volatile("cp.async.wait_group 0;\n"); }
        __syncthreads();

#pragma unroll
        for (int kstep = 0; kstep < 2; kstep++) {
            int k0 = kstep * 16;
            uint32_t a[2][4], bf[4][4];
#pragma unroll
            for (int mt = 0; mt < 2; mt++) {
                uint32_t addr = AsBase + buf * 10240u +
                    (uint32_t)((warpM * 32 + mt * 16 + lr) * 40 + k0 + lc) * 2u;
                ldm_x4(a[mt][0], a[mt][1], a[mt][2], a[mt][3], addr);
            }
#pragma unroll
            for (int g = 0; g < 4; g++) {
                uint32_t addr = BsBase + buf * 10240u +
                    (uint32_t)((warpN * 64 + g * 16 + lr) * 40 + k0 + lc) * 2u;
                ldm_x4(bf[g][0], bf[g][1], bf[g][2], bf[g][3], addr);
            }
#pragma unroll
            for (int mt = 0; mt < 2; mt++)
#pragma unroll
                for (int g = 0; g < 4; g++) {
                    mma16816(acc[mt][g * 2 + 0], a[mt], bf[g][0], bf[g][2]);
                    mma16816(acc[mt][g * 2 + 1], a[mt], bf[g][1], bf[g][3]);
                }
        }
        __syncthreads();
    }

    // ---------------- epilogue: gelu + contract against w2/ws ----------------
#pragma unroll
    for (int mt = 0; mt < 2; mt++) {
#pragma unroll
        for (int r2 = 0; r2 < 2; r2++) {
            float pm = 0.f, ps = 0.f, pw = 0.f;
#pragma unroll
            for (int nf = 0; nf < 8; nf++) {
#pragma unroll
                for (int c01 = 0; c01 < 2; c01++) {
                    int col = warpN * 64 + nf * 8 + (lane & 3) * 2 + c01;
                    float h = gelu_exact(acc[mt][nf][r2 * 2 + c01] + cb1[col]);
                    pm = fmaf(h, cw20[col], pm);
                    ps = fmaf(h, cw21[col], ps);
                    pw = fmaf(h, cwsv[col], pw);
                }
            }
            pm += __shfl_xor_sync(0xffffffffu, pm, 1);
            pm += __shfl_xor_sync(0xffffffffu, pm, 2);
            ps += __shfl_xor_sync(0xffffffffu, ps, 1);
            ps += __shfl_xor_sync(0xffffffffu, ps, 2);
            pw += __shfl_xor_sync(0xffffffffu, pw, 1);
            pw += __shfl_xor_sync(0xffffffffu, pw, 2);
            if ((lane & 3) == 0) {
                int row = warpM * 32 + mt * 16 + (lane >> 2) + r2 * 8;
                red[warpN][row][0] = pm;
                red[warpN][row][1] = ps;
                red[warpN][row][2] = pw;
            }
        }
    }
    __syncthreads();

    if (tid < 128) {
        int row = tid;
        int m = bx * 128 + row;
        float mu  = red[0][row][0] + red[1][row][0];
        float sig = red[0][row][1] + red[1][row][1];
        float wv  = red[0][row][2] + red[1][row][2];
        float* dst = dtile ? g_musig1 : g_musig0;
        dst[((size_t)m * 5 + head) * 2 + 0] = mu;
        dst[((size_t)m * 5 + head) * 2 + 1] = sig;
#pragma unroll
        for (int off = 16; off >= 1; off >>= 1)
            wv += __shfl_xor_sync(0xffffffffu, wv, off);
        if ((tid & 31) == 0) swred[tid >> 5] = wv;
    }
    __syncthreads();
    if (tid == 0) {
        float s = swred[0] + swred[1] + swred[2] + swred[3];
        int b = bx >> 4, mblk = bx & 15;
        g_smpart[((b * 5 + head) * 16 + mblk) * 2 + dtile] = s;
    }
}

// ---------------- Phase 2a: combine d-tile partials + b2 ----------------
__global__ void combine_kernel(const float* __restrict__ b2) {
    int i = blockIdx.x * 256 + threadIdx.x;
    if (i >= 32768 * 5) return;
    float2* p0 = (float2*)g_musig0;
    float2* p1 = (float2*)g_musig1;
    float2 a = p0[i], c = p1[i];
    p0[i] = make_float2(a.x + c.x + b2[0], a.y + c.y + b2[1]);
}

// ---------------- Phase 2b: smooths -> normalized gaussian kernels ----------------
__global__ void reduce_gauss_kernel(const float* __restrict__ bs) {
    int id = threadIdx.x;
    if (id >= 80) return;
    float s = 0.f;
#pragma unroll
    for (int j = 0; j < 32; j++) s += g_smpart[id * 32 + j];
    float sig = s * (1.0f / 2048.0f) + bs[0];
    float denom = sig * sig + 1e-6f;
    float kv[17];
    float ksum = 0.f;
#pragma unroll
    for (int d = 0; d < 17; d++) {
        float t = (float)(d - 8);
        kv[d] = expf(-0.5f * t * t / denom);
        ksum += kv[d];
    }
    float inv = 1.0f / ksum;
#pragma unroll
    for (int d = 0; d < 17; d++) g_gauss[id * 17 + d] = kv[d] * inv;
}

// ---------------- Phase 3: noise generation + temporal gaussian smoothing ----------------
__global__ __launch_bounds__(128) void noise_kernel(
    float* __restrict__ out, int head, int S2, int s2log,
    uint32_t key0, uint32_t key1)
{
    int gid = blockIdx.x * 128 + threadIdx.x;
    int s = gid & (S2 - 1);
    int rest = gid >> s2log;
    int b = rest & 15;
    int chunk = rest >> 4;
    int t0 = chunk * 32;

    float kv[17];
#pragma unroll
    for (int d = 0; d < 17; d++)
        kv[d] = g_gauss[(b * 5 + head) * 17 + d];

    const float2* ms = (const float2*)g_musig0;

    float v[48];
#pragma unroll
    for (int j = 0; j < 48; j++) {
        int t = t0 - 8 + j;
        int tr = (t < 0) ? -t : ((t > 2047) ? (4094 - t) : t);
        int m = b * 2048 + tr;
        float2 p = ms[m * 5 + head];
        uint32_t e = (uint32_t)m * (uint32_t)S2 + (uint32_t)s;
        uint32_t o0, o1;
        threefry2x32(key0, key1, 0u, e, o0, o1);
        v[j] = fmaf(p.y, bits_to_normal(o0 ^ o1), p.x);
    }

    size_t ob = ((size_t)(b * 2048 + t0)) * (size_t)S2 + (size_t)s;
#pragma unroll
    for (int o = 0; o < 32; o++) {
        float a = 0.f;
#pragma unroll
        for (int d = 0; d < 17; d++)
            a = fmaf(kv[d], v[o + d], a);
        out[ob + (size_t)o * S2] = a;
    }
}

// ---------------- launch ----------------
extern "C" void kernel_launch(void* const* d_in, const int* in_sizes, int n_in,
                              void* d_out, int out_size)
{
    const float *x = 0, *w1 = 0, *b1 = 0, *w2 = 0, *b2 = 0, *ws = 0, *bs = 0;
    for (int i = 0; i < n_in; i++) {
        switch (in_sizes[i]) {
            case 16777216: x  = (const float*)d_in[i]; break;
            case 655360:   w1 = (const float*)d_in[i]; break;
            case 1280:     b1 = (const float*)d_in[i]; break;
            case 512:      w2 = (const float*)d_in[i]; break;
            case 256:      ws = (const float*)d_in[i]; break;
            case 2:        b2 = (const float*)d_in[i]; break;
            case 1:        bs = (const float*)d_in[i]; break;
        }
    }
    float* out = (float*)d_out;

    convert_x<<<16384, 256>>>(x);
    convert_w<<<2560, 256>>>(w1);

    dim3 grid(256, 10);
    gemm_mma_kernel<<<grid, 256>>>(b1, w2, ws);
    combine_kernel<<<640, 256>>>(b2);
    reduce_gauss_kernel<<<1, 128>>>(bs);

    size_t off = 0;
    for (int i = 0; i < 5; i++) {
        int S = 4 << i;
        int S2 = S * S;
        int s2log = 4 + 2 * i;
        uint32_t f0, f1;
        threefry2x32(0u, 1u, 0u, (uint32_t)i, f0, f1);
        int total = 16 * S2 * 64;
        noise_kernel<<<total / 128, 128>>>(out + off, i, S2, s2log, f0, f1);
        off += (size_t)16 * 2048 * (size_t)S2;
    }
}

// round 4
// speedup vs baseline: 1.4645x; 1.2607x over previous
#include <cuda_runtime.h>
#include <cuda_bf16.h>
#include <cstdint>

// B=16, T=2048, C=512, H=256, NO=5, R=8

// ---------------- device scratch ----------------
__device__ float g_musig0[32768 * 5 * 2];
__device__ float g_musig1[32768 * 5 * 2];
__device__ float g_smpart[16 * 5 * 16 * 2];
__device__ float g_gauss[16 * 5 * 17];
__device__ __nv_bfloat16 g_xh[16777216];
__device__ __nv_bfloat16 g_xl[16777216];
__device__ __nv_bfloat16 g_wh[655360];   // transposed: [head][d][k]
__device__ __nv_bfloat16 g_wl[655360];

// ---------------- threefry2x32 (JAX-compatible) ----------------
__host__ __device__ __forceinline__ uint32_t rotl32(uint32_t x, uint32_t r) {
    return (x << r) | (x >> (32u - r));
}
__host__ __device__ __forceinline__ void threefry2x32(
    uint32_t k0, uint32_t k1, uint32_t x0, uint32_t x1,
    uint32_t& o0, uint32_t& o1)
{
    uint32_t k2 = k0 ^ k1 ^ 0x1BD11BDAu;
    x0 += k0; x1 += k1;
#define TF_R(r) { x0 += x1; x1 = rotl32(x1, r); x1 ^= x0; }
    TF_R(13) TF_R(15) TF_R(26) TF_R(6)   x0 += k1; x1 += k2 + 1u;
    TF_R(17) TF_R(29) TF_R(16) TF_R(24)  x0 += k2; x1 += k0 + 2u;
    TF_R(13) TF_R(15) TF_R(26) TF_R(6)   x0 += k0; x1 += k1 + 3u;
    TF_R(17) TF_R(29) TF_R(16) TF_R(24)  x0 += k1; x1 += k2 + 4u;
    TF_R(13) TF_R(15) TF_R(26) TF_R(6)   x0 += k2; x1 += k0 + 5u;
#undef TF_R
    o0 = x0; o1 = x1;
}

__device__ __forceinline__ float bits_to_normal(uint32_t bits) {
    float f = __uint_as_float((bits >> 9) | 0x3f800000u) - 1.0f;
    const float LO = -0.99999994f;
    float u = fmaf(f, 2.0f, LO);
    u = fmaxf(LO, u);
    return 1.41421356237f * erfinvf(u);
}

__device__ __forceinline__ float gelu_exact(float v) {
    return 0.5f * v * (1.0f + erff(v * 0.70710678118654752f));
}

// ---------------- PTX helpers ----------------
__device__ __forceinline__ void cp_async16(uint32_t dst, const void* src) {
    asm volatile("cp.async.cg.shared.global [%0], [%1], 16;\n" :: "r"(dst), "l"(src));
}
__device__ __forceinline__ void ldm_x4(uint32_t& r0, uint32_t& r1, uint32_t& r2, uint32_t& r3, uint32_t addr) {
    asm volatile("ldmatrix.sync.aligned.m8n8.x4.shared.b16 {%0,%1,%2,%3}, [%4];\n"
        : "=r"(r0), "=r"(r1), "=r"(r2), "=r"(r3) : "r"(addr));
}
__device__ __forceinline__ void mma16816(float* c, const uint32_t* a, uint32_t b0, uint32_t b1) {
    asm volatile(
        "mma.sync.aligned.m16n8k16.row.col.f32.bf16.bf16.f32 "
        "{%0,%1,%2,%3},{%4,%5,%6,%7},{%8,%9},{%0,%1,%2,%3};\n"
        : "+f"(c[0]), "+f"(c[1]), "+f"(c[2]), "+f"(c[3])
        : "r"(a[0]), "r"(a[1]), "r"(a[2]), "r"(a[3]), "r"(b0), "r"(b1));
}

// ---------------- Phase 0: precision-split conversions ----------------
__global__ __launch_bounds__(256) void convert_x(const float* __restrict__ x) {
    int i = (blockIdx.x * 256 + threadIdx.x) * 4;
    float4 v = *(const float4*)(x + i);
    __nv_bfloat16 h0 = __float2bfloat16_rn(v.x), h1 = __float2bfloat16_rn(v.y);
    __nv_bfloat16 h2 = __float2bfloat16_rn(v.z), h3 = __float2bfloat16_rn(v.w);
    __nv_bfloat16 l0 = __float2bfloat16_rn(v.x - __bfloat162float(h0));
    __nv_bfloat16 l1 = __float2bfloat16_rn(v.y - __bfloat162float(h1));
    __nv_bfloat16 l2 = __float2bfloat16_rn(v.z - __bfloat162float(h2));
    __nv_bfloat16 l3 = __float2bfloat16_rn(v.w - __bfloat162float(h3));
    *(__nv_bfloat162*)(g_xh + i)     = __nv_bfloat162(h0, h1);
    *(__nv_bfloat162*)(g_xh + i + 2) = __nv_bfloat162(h2, h3);
    *(__nv_bfloat162*)(g_xl + i)     = __nv_bfloat162(l0, l1);
    *(__nv_bfloat162*)(g_xl + i + 2) = __nv_bfloat162(l2, l3);
}

__global__ __launch_bounds__(256) void convert_w(const float* __restrict__ w1) {
    int idx = blockIdx.x * 256 + threadIdx.x;    // 655360 total
    if (idx >= 655360) return;
    int head = idx / (512 * 256);
    int r = idx % (512 * 256);
    int k = r / 256, d = r % 256;
    float v = w1[idx];
    __nv_bfloat16 h = __float2bfloat16_rn(v);
    __nv_bfloat16 l = __float2bfloat16_rn(v - __bfloat162float(h));
    int o = head * 131072 + d * 512 + k;
    g_wh[o] = h;
    g_wl[o] = l;
}

// ---------------- Phase 1: bf16 split tensor-core GEMM + fused epilogue ----------------
__global__ __launch_bounds__(256) void gemm_mma_kernel(
    const float* __restrict__ b1, const float* __restrict__ w2,
    const float* __restrict__ ws)
{
    __shared__ __nv_bfloat16 As[2][128 * 40];
    __shared__ __nv_bfloat16 Bs[2][128 * 40];
    __shared__ float cb1[128], cw20[128], cw21[128], cwsv[128];
    __shared__ float red[2][128][3];
    __shared__ float swred[4];

    int tid = threadIdx.x;
    int lane = tid & 31, warp = tid >> 5;
    int warpM = warp >> 1, warpN = warp & 1;
    int bx = blockIdx.x;
    int head = blockIdx.y >> 1;
    int dtile = blockIdx.y & 1;
    int d0 = dtile * 128;

    uint32_t AsBase = (uint32_t)__cvta_generic_to_shared(&As[0][0]);
    uint32_t BsBase = (uint32_t)__cvta_generic_to_shared(&Bs[0][0]);

    if (tid < 128) {
        int d = d0 + tid;
        cb1[tid]  = b1[head * 256 + d];
        cw20[tid] = w2[d * 2 + 0];
        cw21[tid] = w2[d * 2 + 1];
        cwsv[tid] = ws[d];
    }

    int crow = tid >> 2, cc8 = (tid & 3) * 8;

    auto issue = [&](int s, int buf) {
        int term = s >> 4;
        int k0 = (s & 15) * 32;
        const __nv_bfloat16* Asrc = (term == 2) ? g_xl : g_xh;
        const __nv_bfloat16* Bsrc = (term == 1) ? g_wl : g_wh;
#pragma unroll
        for (int it = 0; it < 2; it++) {
            int row = crow + it * 64;
            cp_async16(AsBase + buf * 10240u + (uint32_t)(row * 40 + cc8) * 2u,
                       Asrc + (size_t)(bx * 128 + row) * 512 + k0 + cc8);
            cp_async16(BsBase + buf * 10240u + (uint32_t)(row * 40 + cc8) * 2u,
                       Bsrc + (size_t)head * 131072 + (size_t)(d0 + row) * 512 + k0 + cc8);
        }
        asm volatile("cp.async.commit_group;\n");
    };

    float acc[2][8][4];
#pragma unroll
    for (int mt = 0; mt < 2; mt++)
#pragma unroll
        for (int nf = 0; nf < 8; nf++)
#pragma unroll
            for (int r = 0; r < 4; r++) acc[mt][nf][r] = 0.f;

    int lr = lane & 15, lc = (lane >> 4) * 8;

    issue(0, 0);
    __syncthreads();

    for (int s = 0; s < 48; s++) {
        int buf = s & 1;
        if (s < 47) issue(s + 1, buf ^ 1);
        if (s < 47) { asm volatile("cp.async.wait_group 1;\n"); }
        else        { asm volatile("cp.async.wait_group 0;\n"); }
        __syncthreads();

#pragma unroll
        for (int kstep = 0; kstep < 2; kstep++) {
            int k0 = kstep * 16;
            uint32_t a[2][4], bf[4][4];
#pragma unroll
            for (int mt = 0; mt < 2; mt++) {
                uint32_t addr = AsBase + buf * 10240u +
                    (uint32_t)((warpM * 32 + mt * 16 + lr) * 40 + k0 + lc) * 2u;
                ldm_x4(a[mt][0], a[mt][1], a[mt][2], a[mt][3], addr);
            }
#pragma unroll
            for (int g = 0; g < 4; g++) {
                uint32_t addr = BsBase + buf * 10240u +
                    (uint32_t)((warpN * 64 + g * 16 + lr) * 40 + k0 + lc) * 2u;
                ldm_x4(bf[g][0], bf[g][1], bf[g][2], bf[g][3], addr);
            }
#pragma unroll
            for (int mt = 0; mt < 2; mt++)
#pragma unroll
                for (int g = 0; g < 4; g++) {
                    mma16816(acc[mt][g * 2 + 0], a[mt], bf[g][0], bf[g][2]);
                    mma16816(acc[mt][g * 2 + 1], a[mt], bf[g][1], bf[g][3]);
                }
        }
        __syncthreads();
    }

#pragma unroll
    for (int mt = 0; mt < 2; mt++) {
#pragma unroll
        for (int r2 = 0; r2 < 2; r2++) {
            float pm = 0.f, ps = 0.f, pw = 0.f;
#pragma unroll
            for (int nf = 0; nf < 8; nf++) {
#pragma unroll
                for (int c01 = 0; c01 < 2; c01++) {
                    int col = warpN * 64 + nf * 8 + (lane & 3) * 2 + c01;
                    float h = gelu_exact(acc[mt][nf][r2 * 2 + c01] + cb1[col]);
                    pm = fmaf(h, cw20[col], pm);
                    ps = fmaf(h, cw21[col], ps);
                    pw = fmaf(h, cwsv[col], pw);
                }
            }
            pm += __shfl_xor_sync(0xffffffffu, pm, 1);
            pm += __shfl_xor_sync(0xffffffffu, pm, 2);
            ps += __shfl_xor_sync(0xffffffffu, ps, 1);
            ps += __shfl_xor_sync(0xffffffffu, ps, 2);
            pw += __shfl_xor_sync(0xffffffffu, pw, 1);
            pw += __shfl_xor_sync(0xffffffffu, pw, 2);
            if ((lane & 3) == 0) {
                int row = warpM * 32 + mt * 16 + (lane >> 2) + r2 * 8;
                red[warpN][row][0] = pm;
                red[warpN][row][1] = ps;
                red[warpN][row][2] = pw;
            }
        }
    }
    __syncthreads();

    if (tid < 128) {
        int row = tid;
        int m = bx * 128 + row;
        float mu  = red[0][row][0] + red[1][row][0];
        float sig = red[0][row][1] + red[1][row][1];
        float wv  = red[0][row][2] + red[1][row][2];
        float* dst = dtile ? g_musig1 : g_musig0;
        dst[((size_t)m * 5 + head) * 2 + 0] = mu;
        dst[((size_t)m * 5 + head) * 2 + 1] = sig;
#pragma unroll
        for (int off = 16; off >= 1; off >>= 1)
            wv += __shfl_xor_sync(0xffffffffu, wv, off);
        if ((tid & 31) == 0) swred[tid >> 5] = wv;
    }
    __syncthreads();
    if (tid == 0) {
        float s = swred[0] + swred[1] + swred[2] + swred[3];
        int b = bx >> 4, mblk = bx & 15;
        g_smpart[((b * 5 + head) * 16 + mblk) * 2 + dtile] = s;
    }
}

// ---------------- Phase 2a: combine d-tile partials + b2 ----------------
__global__ void combine_kernel(const float* __restrict__ b2) {
    int i = blockIdx.x * 256 + threadIdx.x;
    if (i >= 32768 * 5) return;
    float2* p0 = (float2*)g_musig0;
    float2* p1 = (float2*)g_musig1;
    float2 a = p0[i], c = p1[i];
    p0[i] = make_float2(a.x + c.x + b2[0], a.y + c.y + b2[1]);
}

// ---------------- Phase 2b: smooths -> normalized gaussian kernels ----------------
__global__ void reduce_gauss_kernel(const float* __restrict__ bs) {
    int id = threadIdx.x;
    if (id >= 80) return;
    float s = 0.f;
#pragma unroll
    for (int j = 0; j < 32; j++) s += g_smpart[id * 32 + j];
    float sig = s * (1.0f / 2048.0f) + bs[0];
    float denom = sig * sig + 1e-6f;
    float kv[17];
    float ksum = 0.f;
#pragma unroll
    for (int d = 0; d < 17; d++) {
        float t = (float)(d - 8);
        kv[d] = expf(-0.5f * t * t / denom);
        ksum += kv[d];
    }
    float inv = 1.0f / ksum;
#pragma unroll
    for (int d = 0; d < 17; d++) g_gauss[id * 17 + d] = kv[d] * inv;
}

// ---------------- Phase 3: tiled noise + smoothing (smem window sharing) ----------------
// Block tile: (b fixed) x (TT time steps) x (SW spatial cols). Window (TT+16)xSW built
// once in smem (recompute 1+16/TT), then each thread convolves 16 outputs from a
// 32-value register window (2 smem reads / output). Coalesced stores.
template<int SW, int TT>
__global__ __launch_bounds__(256) void noise_tile_kernel(
    float* __restrict__ out, int head, int S2,
    uint32_t key0, uint32_t key1)
{
    constexpr int W = TT + 16;
    __shared__ float vbuf[W * SW];

    int tid = threadIdx.x;
    int s0 = blockIdx.x * SW;
    int t0 = blockIdx.y * TT;
    int b  = blockIdx.z;

    // gaussian kernel (warp-uniform broadcast loads)
    float kv[17];
#pragma unroll
    for (int d = 0; d < 17; d++)
        kv[d] = g_gauss[(b * 5 + head) * 17 + d];

    const float2* ms = (const float2*)g_musig0;

    // ---- phase 1: generate window ----
    constexpr int GEN_IT = (W * SW + 255) / 256;
#pragma unroll
    for (int it = 0; it < GEN_IT; it++) {
        int j = tid + it * 256;
        if (W * SW % 256 != 0 && j >= W * SW) break;
        int tt = j / SW;
        int ss = j - tt * SW;
        int t = t0 - 8 + tt;
        int tr = (t < 0) ? -t : ((t > 2047) ? (4094 - t) : t);
        int m = b * 2048 + tr;
        float2 p = ms[m * 5 + head];                 // warp-uniform for SW>=32
        uint32_t e = (uint32_t)m * (uint32_t)S2 + (uint32_t)(s0 + ss);
        uint32_t o0, o1;
        threefry2x32(key0, key1, 0u, e, o0, o1);
        vbuf[j] = fmaf(p.y, bits_to_normal(o0 ^ o1), p.x);
    }
    __syncthreads();

    // ---- phase 2: 17-tap conv, 16 outputs/thread ----
    int os  = tid & (SW - 1);
    int grp = tid / SW;          // TT/16 groups
    int ot0 = grp * 16;

    float w[32];
#pragma unroll
    for (int j = 0; j < 32; j++)
        w[j] = vbuf[(ot0 + j) * SW + os];

    size_t ob = ((size_t)(b * 2048 + t0 + ot0)) * (size_t)S2 + (size_t)(s0 + os);
#pragma unroll
    for (int o = 0; o < 16; o++) {
        float a = 0.f;
#pragma unroll
        for (int d = 0; d < 17; d++)
            a = fmaf(kv[d], w[o + d], a);
        out[ob + (size_t)o * S2] = a;
    }
}

// ---------------- launch ----------------
extern "C" void kernel_launch(void* const* d_in, const int* in_sizes, int n_in,
                              void* d_out, int out_size)
{
    const float *x = 0, *w1 = 0, *b1 = 0, *w2 = 0, *b2 = 0, *ws = 0, *bs = 0;
    for (int i = 0; i < n_in; i++) {
        switch (in_sizes[i]) {
            case 16777216: x  = (const float*)d_in[i]; break;
            case 655360:   w1 = (const float*)d_in[i]; break;
            case 1280:     b1 = (const float*)d_in[i]; break;
            case 512:      w2 = (const float*)d_in[i]; break;
            case 256:      ws = (const float*)d_in[i]; break;
            case 2:        b2 = (const float*)d_in[i]; break;
            case 1:        bs = (const float*)d_in[i]; break;
        }
    }
    float* out = (float*)d_out;

    convert_x<<<16384, 256>>>(x);
    convert_w<<<2560, 256>>>(w1);

    dim3 grid(256, 10);
    gemm_mma_kernel<<<grid, 256>>>(b1, w2, ws);
    combine_kernel<<<640, 256>>>(b2);
    reduce_gauss_kernel<<<1, 128>>>(bs);

    size_t off = 0;
    for (int i = 0; i < 5; i++) {
        int S = 4 << i;
        int S2 = S * S;
        uint32_t f0, f1;
        threefry2x32(0u, 1u, 0u, (uint32_t)i, f0, f1);
        if (i == 0) {
            // S2 = 16: SW=16, TT=256
            dim3 g(1, 2048 / 256, 16);
            noise_tile_kernel<16, 256><<<g, 256>>>(out + off, i, S2, f0, f1);
        } else {
            dim3 g(S2 / 32, 2048 / 128, 16);
            noise_tile_kernel<32, 128><<<g, 256>>>(out + off, i, S2, f0, f1);
        }
        off += (size_t)16 * 2048 * (size_t)S2;
    }
}

// round 5
// speedup vs baseline: 1.5664x; 1.0696x over previous
#include <cuda_runtime.h>
#include <cuda_bf16.h>
#include <cstdint>

// B=16, T=2048, C=512, H=256, NO=5, R=8

// ---------------- device scratch ----------------
__device__ float g_musig0[32768 * 5 * 2];
__device__ float g_musig1[32768 * 5 * 2];
__device__ float g_smpart[16 * 5 * 16 * 2];
__device__ float g_gauss[16 * 5 * 17];
__device__ __nv_bfloat16 g_xh[16777216];
__device__ __nv_bfloat16 g_xl[16777216];
__device__ __nv_bfloat16 g_wh[655360];   // transposed: [head][d][k]
__device__ __nv_bfloat16 g_wl[655360];

// ---------------- threefry2x32 (JAX-compatible) ----------------
__host__ __device__ __forceinline__ uint32_t rotl32(uint32_t x, uint32_t r) {
    return (x << r) | (x >> (32u - r));
}
__host__ __device__ __forceinline__ void threefry2x32(
    uint32_t k0, uint32_t k1, uint32_t x0, uint32_t x1,
    uint32_t& o0, uint32_t& o1)
{
    uint32_t k2 = k0 ^ k1 ^ 0x1BD11BDAu;
    x0 += k0; x1 += k1;
#define TF_R(r) { x0 += x1; x1 = rotl32(x1, r); x1 ^= x0; }
    TF_R(13) TF_R(15) TF_R(26) TF_R(6)   x0 += k1; x1 += k2 + 1u;
    TF_R(17) TF_R(29) TF_R(16) TF_R(24)  x0 += k2; x1 += k0 + 2u;
    TF_R(13) TF_R(15) TF_R(26) TF_R(6)   x0 += k0; x1 += k1 + 3u;
    TF_R(17) TF_R(29) TF_R(16) TF_R(24)  x0 += k1; x1 += k2 + 4u;
    TF_R(13) TF_R(15) TF_R(26) TF_R(6)   x0 += k2; x1 += k0 + 5u;
#undef TF_R
    o0 = x0; o1 = x1;
}

__device__ __forceinline__ float bits_to_normal(uint32_t bits) {
    float f = __uint_as_float((bits >> 9) | 0x3f800000u) - 1.0f;
    const float LO = -0.99999994f;
    float u = fmaf(f, 2.0f, LO);
    u = fmaxf(LO, u);
    return 1.41421356237f * erfinvf(u);
}

__device__ __forceinline__ float gelu_exact(float v) {
    return 0.5f * v * (1.0f + erff(v * 0.70710678118654752f));
}

// ---------------- PTX helpers ----------------
__device__ __forceinline__ void cp_async16(uint32_t dst, const void* src) {
    asm volatile("cp.async.cg.shared.global [%0], [%1], 16;\n" :: "r"(dst), "l"(src));
}
__device__ __forceinline__ void ldm_x4(uint32_t& r0, uint32_t& r1, uint32_t& r2, uint32_t& r3, uint32_t addr) {
    asm volatile("ldmatrix.sync.aligned.m8n8.x4.shared.b16 {%0,%1,%2,%3}, [%4];\n"
        : "=r"(r0), "=r"(r1), "=r"(r2), "=r"(r3) : "r"(addr));
}
__device__ __forceinline__ void mma16816(float* c, const uint32_t* a, uint32_t b0, uint32_t b1) {
    asm volatile(
        "mma.sync.aligned.m16n8k16.row.col.f32.bf16.bf16.f32 "
        "{%0,%1,%2,%3},{%4,%5,%6,%7},{%8,%9},{%0,%1,%2,%3};\n"
        : "+f"(c[0]), "+f"(c[1]), "+f"(c[2]), "+f"(c[3])
        : "r"(a[0]), "r"(a[1]), "r"(a[2]), "r"(a[3]), "r"(b0), "r"(b1));
}
#define PACK_F32X2(out, lo, hi) \
    asm("mov.b64 %0, {%1, %2};" : "=l"(out) : "f"(lo), "f"(hi))
#define UNPACK_F32X2(lo, hi, in) \
    asm("mov.b64 {%0, %1}, %2;" : "=f"(lo), "=f"(hi) : "l"(in))
#define FMA_F32X2(d, a, b, c) \
    asm("fma.rn.f32x2 %0, %1, %2, %3;" : "=l"(d) : "l"(a), "l"(b), "l"(c))

// ---------------- Phase 0: precision-split conversions ----------------
__global__ __launch_bounds__(256) void convert_x(const float* __restrict__ x) {
    int i = (blockIdx.x * 256 + threadIdx.x) * 4;
    float4 v = *(const float4*)(x + i);
    __nv_bfloat16 h0 = __float2bfloat16_rn(v.x), h1 = __float2bfloat16_rn(v.y);
    __nv_bfloat16 h2 = __float2bfloat16_rn(v.z), h3 = __float2bfloat16_rn(v.w);
    __nv_bfloat16 l0 = __float2bfloat16_rn(v.x - __bfloat162float(h0));
    __nv_bfloat16 l1 = __float2bfloat16_rn(v.y - __bfloat162float(h1));
    __nv_bfloat16 l2 = __float2bfloat16_rn(v.z - __bfloat162float(h2));
    __nv_bfloat16 l3 = __float2bfloat16_rn(v.w - __bfloat162float(h3));
    *(__nv_bfloat162*)(g_xh + i)     = __nv_bfloat162(h0, h1);
    *(__nv_bfloat162*)(g_xh + i + 2) = __nv_bfloat162(h2, h3);
    *(__nv_bfloat162*)(g_xl + i)     = __nv_bfloat162(l0, l1);
    *(__nv_bfloat162*)(g_xl + i + 2) = __nv_bfloat162(l2, l3);
}

__global__ __launch_bounds__(256) void convert_w(const float* __restrict__ w1) {
    int idx = blockIdx.x * 256 + threadIdx.x;    // 655360 total
    if (idx >= 655360) return;
    int head = idx / (512 * 256);
    int r = idx % (512 * 256);
    int k = r / 256, d = r % 256;
    float v = w1[idx];
    __nv_bfloat16 h = __float2bfloat16_rn(v);
    __nv_bfloat16 l = __float2bfloat16_rn(v - __bfloat162float(h));
    int o = head * 131072 + d * 512 + k;
    g_wh[o] = h;
    g_wl[o] = l;
}

// ---------------- Phase 1: bf16 split tensor-core GEMM + fused epilogue ----------------
__global__ __launch_bounds__(256) void gemm_mma_kernel(
    const float* __restrict__ b1, const float* __restrict__ w2,
    const float* __restrict__ ws)
{
    __shared__ __nv_bfloat16 As[2][128 * 40];
    __shared__ __nv_bfloat16 Bs[2][128 * 40];
    __shared__ float cb1[128], cw20[128], cw21[128], cwsv[128];
    __shared__ float red[2][128][3];
    __shared__ float swred[4];

    int tid = threadIdx.x;
    int lane = tid & 31, warp = tid >> 5;
    int warpM = warp >> 1, warpN = warp & 1;
    int bx = blockIdx.x;
    int head = blockIdx.y >> 1;
    int dtile = blockIdx.y & 1;
    int d0 = dtile * 128;

    uint32_t AsBase = (uint32_t)__cvta_generic_to_shared(&As[0][0]);
    uint32_t BsBase = (uint32_t)__cvta_generic_to_shared(&Bs[0][0]);

    if (tid < 128) {
        int d = d0 + tid;
        cb1[tid]  = b1[head * 256 + d];
        cw20[tid] = w2[d * 2 + 0];
        cw21[tid] = w2[d * 2 + 1];
        cwsv[tid] = ws[d];
    }

    int crow = tid >> 2, cc8 = (tid & 3) * 8;

    auto issue = [&](int s, int buf) {
        int term = s >> 4;
        int k0 = (s & 15) * 32;
        const __nv_bfloat16* Asrc = (term == 2) ? g_xl : g_xh;
        const __nv_bfloat16* Bsrc = (term == 1) ? g_wl : g_wh;
#pragma unroll
        for (int it = 0; it < 2; it++) {
            int row = crow + it * 64;
            cp_async16(AsBase + buf * 10240u + (uint32_t)(row * 40 + cc8) * 2u,
                       Asrc + (size_t)(bx * 128 + row) * 512 + k0 + cc8);
            cp_async16(BsBase + buf * 10240u + (uint32_t)(row * 40 + cc8) * 2u,
                       Bsrc + (size_t)head * 131072 + (size_t)(d0 + row) * 512 + k0 + cc8);
        }
        asm volatile("cp.async.commit_group;\n");
    };

    float acc[2][8][4];
#pragma unroll
    for (int mt = 0; mt < 2; mt++)
#pragma unroll
        for (int nf = 0; nf < 8; nf++)
#pragma unroll
            for (int r = 0; r < 4; r++) acc[mt][nf][r] = 0.f;

    int lr = lane & 15, lc = (lane >> 4) * 8;

    issue(0, 0);
    __syncthreads();

    for (int s = 0; s < 48; s++) {
        int buf = s & 1;
        if (s < 47) issue(s + 1, buf ^ 1);
        if (s < 47) { asm volatile("cp.async.wait_group 1;\n"); }
        else        { asm volatile("cp.async.wait_group 0;\n"); }
        __syncthreads();

#pragma unroll
        for (int kstep = 0; kstep < 2; kstep++) {
            int k0 = kstep * 16;
            uint32_t a[2][4], bf[4][4];
#pragma unroll
            for (int mt = 0; mt < 2; mt++) {
                uint32_t addr = AsBase + buf * 10240u +
                    (uint32_t)((warpM * 32 + mt * 16 + lr) * 40 + k0 + lc) * 2u;
                ldm_x4(a[mt][0], a[mt][1], a[mt][2], a[mt][3], addr);
            }
#pragma unroll
            for (int g = 0; g < 4; g++) {
                uint32_t addr = BsBase + buf * 10240u +
                    (uint32_t)((warpN * 64 + g * 16 + lr) * 40 + k0 + lc) * 2u;
                ldm_x4(bf[g][0], bf[g][1], bf[g][2], bf[g][3], addr);
            }
#pragma unroll
            for (int mt = 0; mt < 2; mt++)
#pragma unroll
                for (int g = 0; g < 4; g++) {
                    mma16816(acc[mt][g * 2 + 0], a[mt], bf[g][0], bf[g][2]);
                    mma16816(acc[mt][g * 2 + 1], a[mt], bf[g][1], bf[g][3]);
                }
        }
        __syncthreads();
    }

#pragma unroll
    for (int mt = 0; mt < 2; mt++) {
#pragma unroll
        for (int r2 = 0; r2 < 2; r2++) {
            float pm = 0.f, ps = 0.f, pw = 0.f;
#pragma unroll
            for (int nf = 0; nf < 8; nf++) {
#pragma unroll
                for (int c01 = 0; c01 < 2; c01++) {
                    int col = warpN * 64 + nf * 8 + (lane & 3) * 2 + c01;
                    float h = gelu_exact(acc[mt][nf][r2 * 2 + c01] + cb1[col]);
                    pm = fmaf(h, cw20[col], pm);
                    ps = fmaf(h, cw21[col], ps);
                    pw = fmaf(h, cwsv[col], pw);
                }
            }
            pm += __shfl_xor_sync(0xffffffffu, pm, 1);
            pm += __shfl_xor_sync(0xffffffffu, pm, 2);
            ps += __shfl_xor_sync(0xffffffffu, ps, 1);
            ps += __shfl_xor_sync(0xffffffffu, ps, 2);
            pw += __shfl_xor_sync(0xffffffffu, pw, 1);
            pw += __shfl_xor_sync(0xffffffffu, pw, 2);
            if ((lane & 3) == 0) {
                int row = warpM * 32 + mt * 16 + (lane >> 2) + r2 * 8;
                red[warpN][row][0] = pm;
                red[warpN][row][1] = ps;
                red[warpN][row][2] = pw;
            }
        }
    }
    __syncthreads();

    if (tid < 128) {
        int row = tid;
        int m = bx * 128 + row;
        float mu  = red[0][row][0] + red[1][row][0];
        float sig = red[0][row][1] + red[1][row][1];
        float wv  = red[0][row][2] + red[1][row][2];
        float* dst = dtile ? g_musig1 : g_musig0;
        dst[((size_t)m * 5 + head) * 2 + 0] = mu;
        dst[((size_t)m * 5 + head) * 2 + 1] = sig;
#pragma unroll
        for (int off = 16; off >= 1; off >>= 1)
            wv += __shfl_xor_sync(0xffffffffu, wv, off);
        if ((tid & 31) == 0) swred[tid >> 5] = wv;
    }
    __syncthreads();
    if (tid == 0) {
        float s = swred[0] + swred[1] + swred[2] + swred[3];
        int b = bx >> 4, mblk = bx & 15;
        g_smpart[((b * 5 + head) * 16 + mblk) * 2 + dtile] = s;
    }
}

// ---------------- Phase 2a: combine d-tile partials + b2 ----------------
__global__ void combine_kernel(const float* __restrict__ b2) {
    int i = blockIdx.x * 256 + threadIdx.x;
    if (i >= 32768 * 5) return;
    float2* p0 = (float2*)g_musig0;
    float2* p1 = (float2*)g_musig1;
    float2 a = p0[i], c = p1[i];
    p0[i] = make_float2(a.x + c.x + b2[0], a.y + c.y + b2[1]);
}

// ---------------- Phase 2b: smooths -> normalized gaussian kernels ----------------
__global__ void reduce_gauss_kernel(const float* __restrict__ bs) {
    int id = threadIdx.x;
    if (id >= 80) return;
    float s = 0.f;
#pragma unroll
    for (int j = 0; j < 32; j++) s += g_smpart[id * 32 + j];
    float sig = s * (1.0f / 2048.0f) + bs[0];
    float denom = sig * sig + 1e-6f;
    float kv[17];
    float ksum = 0.f;
#pragma unroll
    for (int d = 0; d < 17; d++) {
        float t = (float)(d - 8);
        kv[d] = expf(-0.5f * t * t / denom);
        ksum += kv[d];
    }
    float inv = 1.0f / ksum;
#pragma unroll
    for (int d = 0; d < 17; d++) g_gauss[id * 17 + d] = kv[d] * inv;
}

// ---------------- Phase 3a: big-head noise kernel (SW=32, TT=256, 512 threads) ----------------
// Window (TT+16)x32 in smem (halo 6.25%); conv uses packed f32x2 FMA: outputs o and o+8
// share accumulation via pw[j] = (w[j], w[j+8]).
__global__ __launch_bounds__(512) void noise_tile2_kernel(
    float* __restrict__ out, int head, int S2,
    uint32_t key0, uint32_t key1)
{
    constexpr int SW = 32;
    constexpr int TT = 256;
    constexpr int W = TT + 16;            // 272
    __shared__ float vbuf[W * SW];        // 34816 B

    int tid = threadIdx.x;
    int s0 = blockIdx.x * SW;
    int t0 = blockIdx.y * TT;
    int b  = blockIdx.z;

    float kv[17];
#pragma unroll
    for (int d = 0; d < 17; d++)
        kv[d] = g_gauss[(b * 5 + head) * 17 + d];

    const float2* ms = (const float2*)g_musig0;

    // ---- gen: 272 rows x 32 cols, 16 rows per iteration x 17 iterations ----
    int ss = tid & 31;
    int r0 = tid >> 5;
#pragma unroll
    for (int it = 0; it < W / 16; it++) {
        int tt = it * 16 + r0;
        int t = t0 - 8 + tt;
        int tr = (t < 0) ? -t : ((t > 2047) ? (4094 - t) : t);
        int m = b * 2048 + tr;
        float2 p = ms[m * 5 + head];      // warp-uniform broadcast
        uint32_t e = (uint32_t)m * (uint32_t)S2 + (uint32_t)(s0 + ss);
        uint32_t o0, o1;
        threefry2x32(key0, key1, 0u, e, o0, o1);
        vbuf[tt * SW + ss] = fmaf(p.y, bits_to_normal(o0 ^ o1), p.x);
    }
    __syncthreads();

    // ---- conv: 512 threads, each 16 outputs (paired o / o+8 via f32x2) ----
    int os  = tid & 31;
    int grp = tid >> 5;                   // 0..15
    int ot0 = grp * 16;

    float w[32];
#pragma unroll
    for (int j = 0; j < 32; j++)
        w[j] = vbuf[(ot0 + j) * SW + os];

    unsigned long long kk[17];
#pragma unroll
    for (int d = 0; d < 17; d++)
        PACK_F32X2(kk[d], kv[d], kv[d]);

    unsigned long long pw[24];
#pragma unroll
    for (int j = 0; j < 24; j++)
        PACK_F32X2(pw[j], w[j], w[j + 8]);

    size_t ob = ((size_t)(b * 2048 + t0 + ot0)) * (size_t)S2 + (size_t)(s0 + os);
#pragma unroll
    for (int o = 0; o < 8; o++) {
        unsigned long long acc;
        PACK_F32X2(acc, 0.0f, 0.0f);
#pragma unroll
        for (int d = 0; d < 17; d++)
            FMA_F32X2(acc, kk[d], pw[o + d], acc);
        float lo, hi;
        UNPACK_F32X2(lo, hi, acc);
        __stcs(out + ob + (size_t)o * S2, lo);
        __stcs(out + ob + (size_t)(o + 8) * S2, hi);
    }
}

// ---------------- Phase 3b: head-0 noise kernel (SW=16, TT=256, 256 threads) ----------------
template<int SW, int TT>
__global__ __launch_bounds__(256) void noise_tile_kernel(
    float* __restrict__ out, int head, int S2,
    uint32_t key0, uint32_t key1)
{
    constexpr int W = TT + 16;
    __shared__ float vbuf[W * SW];

    int tid = threadIdx.x;
    int s0 = blockIdx.x * SW;
    int t0 = blockIdx.y * TT;
    int b  = blockIdx.z;

    float kv[17];
#pragma unroll
    for (int d = 0; d < 17; d++)
        kv[d] = g_gauss[(b * 5 + head) * 17 + d];

    const float2* ms = (const float2*)g_musig0;

    constexpr int GEN_IT = (W * SW + 255) / 256;
#pragma unroll
    for (int it = 0; it < GEN_IT; it++) {
        int j = tid + it * 256;
        if (W * SW % 256 != 0 && j >= W * SW) break;
        int tt = j / SW;
        int ss = j - tt * SW;
        int t = t0 - 8 + tt;
        int tr = (t < 0) ? -t : ((t > 2047) ? (4094 - t) : t);
        int m = b * 2048 + tr;
        float2 p = ms[m * 5 + head];
        uint32_t e = (uint32_t)m * (uint32_t)S2 + (uint32_t)(s0 + ss);
        uint32_t o0, o1;
        threefry2x32(key0, key1, 0u, e, o0, o1);
        vbuf[j] = fmaf(p.y, bits_to_normal(o0 ^ o1), p.x);
    }
    __syncthreads();

    int os  = tid & (SW - 1);
    int grp = tid / SW;
    int ot0 = grp * 16;

    float w[32];
#pragma unroll
    for (int j = 0; j < 32; j++)
        w[j] = vbuf[(ot0 + j) * SW + os];

    size_t ob = ((size_t)(b * 2048 + t0 + ot0)) * (size_t)S2 + (size_t)(s0 + os);
#pragma unroll
    for (int o = 0; o < 16; o++) {
        float a = 0.f;
#pragma unroll
        for (int d = 0; d < 17; d++)
            a = fmaf(kv[d], w[o + d], a);
        __stcs(out + ob + (size_t)o * S2, a);
    }
}

// ---------------- launch ----------------
extern "C" void kernel_launch(void* const* d_in, const int* in_sizes, int n_in,
                              void* d_out, int out_size)
{
    const float *x = 0, *w1 = 0, *b1 = 0, *w2 = 0, *b2 = 0, *ws = 0, *bs = 0;
    for (int i = 0; i < n_in; i++) {
        switch (in_sizes[i]) {
            case 16777216: x  = (const float*)d_in[i]; break;
            case 655360:   w1 = (const float*)d_in[i]; break;
            case 1280:     b1 = (const float*)d_in[i]; break;
            case 512:      w2 = (const float*)d_in[i]; break;
            case 256:      ws = (const float*)d_in[i]; break;
            case 2:        b2 = (const float*)d_in[i]; break;
            case 1:        bs = (const float*)d_in[i]; break;
        }
    }
    float* out = (float*)d_out;

    convert_x<<<16384, 256>>>(x);
    convert_w<<<2560, 256>>>(w1);

    dim3 grid(256, 10);
    gemm_mma_kernel<<<grid, 256>>>(b1, w2, ws);
    combine_kernel<<<640, 256>>>(b2);
    reduce_gauss_kernel<<<1, 128>>>(bs);

    // per-head output offsets
    size_t offs[5];
    size_t off = 0;
    for (int i = 0; i < 5; i++) {
        int S2 = (4 << i) * (4 << i);
        offs[i] = off;
        off += (size_t)16 * 2048 * (size_t)S2;
    }

    // launch largest head first (also lets ncu -s5 -c1 capture head 4)
    for (int i = 4; i >= 0; i--) {
        int S2 = (4 << i) * (4 << i);
        uint32_t f0, f1;
        threefry2x32(0u, 1u, 0u, (uint32_t)i, f0, f1);
        if (i == 0) {
            dim3 g(1, 2048 / 256, 16);
            noise_tile_kernel<16, 256><<<g, 256>>>(out + offs[i], i, S2, f0, f1);
        } else {
            dim3 g(S2 / 32, 2048 / 256, 16);
            noise_tile2_kernel<<<g, 512>>>(out + offs[i], i, S2, f0, f1);
        }
    }
}